// round 14
// baseline (speedup 1.0000x reference)
#include <cuda_runtime.h>
#include <cuda_bf16.h>
#include <math.h>
#include <stdint.h>

#define NROW 8192
#define DDIM 256
#define KINST 16
#define KNEG 4088   // (N-K)/2
#define KPOS 8      // K/2

// Scratch (device globals: allocation-free per harness rules)
__device__ float g_d2[(size_t)NROW * NROW];  // 256 MB pairwise clipped squared distances
__device__ float g_sq[NROW];
__device__ float g_diff[NROW];

// ---------------------------------------------------------------------------
// Kernel 1: row squared norms. One warp per row.
// ---------------------------------------------------------------------------
__global__ __launch_bounds__(256) void sq_kernel(const float* __restrict__ X) {
    int row = blockIdx.x * 8 + (threadIdx.x >> 5);
    int lane = threadIdx.x & 31;
    const float* r = X + (size_t)row * DDIM;
    float s = 0.f;
#pragma unroll
    for (int c = lane; c < DDIM; c += 32) {
        float v = r[c];
        s = fmaf(v, v, s);
    }
#pragma unroll
    for (int o = 16; o; o >>= 1) s += __shfl_xor_sync(0xffffffffu, s, o);
    if (lane == 0) g_sq[row] = s;
}

// ---------------------------------------------------------------------------
// Kernel 2: fp32 GEMM  G = X X^T  with fused epilogue
//           d2[i][j] = max(sq_i + sq_j - 2*G_ij, 1e-12)
// 128x128 tile, BK=16, 256 threads, 8x8 micro-tile per thread.
// ---------------------------------------------------------------------------
__global__ __launch_bounds__(256) void gemm_d2_kernel(const float* __restrict__ X) {
    const int BM = 128, BN = 128, BK = 16;
    __shared__ float As[BK][BM + 4];
    __shared__ float Bs[BK][BN + 4];

    const int bi = blockIdx.y * BM;
    const int bj = blockIdx.x * BN;
    const int tid = threadIdx.x;
    const int ty = tid >> 4;        // 0..15
    const int tx = tid & 15;        // 0..15

    float acc[8][8];
#pragma unroll
    for (int r = 0; r < 8; ++r)
#pragma unroll
        for (int c = 0; c < 8; ++c) acc[r][c] = 0.f;

    for (int k0 = 0; k0 < DDIM; k0 += BK) {
        // Load 128x16 A-tile and B-tile, transposed into smem (k-major).
#pragma unroll
        for (int qq = 0; qq < 2; ++qq) {
            int q   = tid + qq * 256;     // 0..511 float4 slots
            int row = q >> 2;             // 0..127
            int c4  = (q & 3) * 4;        // 0,4,8,12
            float4 va = *(const float4*)(X + (size_t)(bi + row) * DDIM + k0 + c4);
            As[c4 + 0][row] = va.x; As[c4 + 1][row] = va.y;
            As[c4 + 2][row] = va.z; As[c4 + 3][row] = va.w;
            float4 vb = *(const float4*)(X + (size_t)(bj + row) * DDIM + k0 + c4);
            Bs[c4 + 0][row] = vb.x; Bs[c4 + 1][row] = vb.y;
            Bs[c4 + 2][row] = vb.z; Bs[c4 + 3][row] = vb.w;
        }
        __syncthreads();

#pragma unroll
        for (int kk = 0; kk < BK; ++kk) {
            float a[8], b[8];
#pragma unroll
            for (int u = 0; u < 8; ++u) a[u] = As[kk][ty * 8 + u];
#pragma unroll
            for (int u = 0; u < 8; ++u) b[u] = Bs[kk][tx * 8 + u];
#pragma unroll
            for (int r = 0; r < 8; ++r)
#pragma unroll
                for (int c = 0; c < 8; ++c)
                    acc[r][c] = fmaf(a[r], b[c], acc[r][c]);
        }
        __syncthreads();
    }

    // Epilogue: d2 = clip(sq_i + sq_j - 2*dot, 1e-12)
    float sqi[8], sqj[8];
#pragma unroll
    for (int u = 0; u < 8; ++u) {
        sqi[u] = g_sq[bi + ty * 8 + u];
        sqj[u] = g_sq[bj + tx * 8 + u];
    }
#pragma unroll
    for (int r = 0; r < 8; ++r) {
        size_t base = (size_t)(bi + ty * 8 + r) * NROW + bj + tx * 8;
        float v[8];
#pragma unroll
        for (int c = 0; c < 8; ++c)
            v[c] = fmaxf(sqi[r] + sqj[c] - 2.0f * acc[r][c], 1e-12f);
        *(float4*)(g_d2 + base)     = make_float4(v[0], v[1], v[2], v[3]);
        *(float4*)(g_d2 + base + 4) = make_float4(v[4], v[5], v[6], v[7]);
    }
}

// ---------------------------------------------------------------------------
// Kernel 3: per-row selection. One CTA (256 threads) per row.
//  - row d2 loaded once into SMEM (32 KB)
//  - rn^2 = sum of clipped d2 (deterministic tree reduce)
//  - positives = 16 columns of the row's identity group (saved, then zeroed)
//  - exact radix-select of the KNEG-th largest d2 among negatives
//  - 8th-largest of the 16 positives via sort
//  - emit |sqrt(an)-sqrt(ap)| * scale(rn)
// ---------------------------------------------------------------------------
__global__ __launch_bounds__(256) void select_kernel() {
    __shared__ float row[NROW];          // 32 KB
    __shared__ unsigned hist[256];
    __shared__ float red[256];
    __shared__ float pos_s[KINST];
    __shared__ unsigned s_prefix, s_k;

    const int i   = blockIdx.x;
    const int tid = threadIdx.x;

    // Load the row (float4 coalesced)
    const float4* src = (const float4*)(g_d2 + (size_t)i * NROW);
    float4* rw = (float4*)row;
    for (int q = tid; q < NROW / 4; q += 256) rw[q] = src[q];
    __syncthreads();

    // rn^2 : deterministic block reduce
    float s = 0.f;
    for (int q = tid; q < NROW; q += 256) s += row[q];
    red[tid] = s;
    __syncthreads();
#pragma unroll
    for (int off = 128; off; off >>= 1) {
        if (tid < off) red[tid] += red[tid + off];
        __syncthreads();
    }

    // Extract positives (same identity group), then zero them out
    const int g0 = i & ~(KINST - 1);
    if (tid < KINST) pos_s[tid] = row[g0 + tid];
    __syncthreads();
    if (tid < KINST) row[g0 + tid] = 0.0f;   // pattern 0 < any clipped d2
    if (tid == 0) { s_prefix = 0u; s_k = KNEG; }
    __syncthreads();

    // Exact radix select (4 x 8-bit, MSB first) of k-th largest.
    // All values >= 1e-12 > 0, so float order == uint32 order of bit patterns.
#pragma unroll 1
    for (int pass = 3; pass >= 0; --pass) {
        hist[tid] = 0u;
        __syncthreads();
        const unsigned prefix = s_prefix;
        const int shift = pass * 8;
        const unsigned himask = (pass == 3) ? 0u : (0xFFFFFFFFu << (shift + 8));
        const unsigned lane = tid & 31;

        for (int q = tid; q < NROW; q += 256) {   // uniform trip count per warp
            unsigned b = __float_as_uint(row[q]);
            unsigned key = ((b & himask) == prefix) ? ((b >> shift) & 0xFFu)
                                                    : 0xFFFFFFFFu;
            unsigned m = __match_any_sync(0xFFFFFFFFu, key);
            // lowest lane with this key does the aggregated add
            if (key != 0xFFFFFFFFu && (((1u << lane) - 1u) & m) == 0u)
                atomicAdd(&hist[key], (unsigned)__popc(m));
        }
        __syncthreads();

        if (tid == 0) {
            unsigned cum = 0, kk = s_k, sel = 0;
            for (int d = 255; d >= 0; --d) {
                unsigned h = hist[d];
                if (cum + h >= kk) { sel = (unsigned)d; s_k = kk - cum; break; }
                cum += h;
            }
            s_prefix = prefix | (sel << shift);
        }
        __syncthreads();
    }

    if (tid == 0) {
        float an_d2 = __uint_as_float(s_prefix);

        // 8th largest of the 16 positives
        float p[KINST];
#pragma unroll
        for (int u = 0; u < KINST; ++u) p[u] = pos_s[u];
#pragma unroll
        for (int a = 1; a < KINST; ++a) {          // insertion sort, descending
            float v = p[a];
            int b = a - 1;
            while (b >= 0 && p[b] < v) { p[b + 1] = p[b]; --b; }
            p[b + 1] = v;
        }
        float ap_d2 = p[KPOS - 1];

        float rn = sqrtf(red[0]);
        float scale = (rn > 1e-5f ? 1e-5f / rn : 1.0f) * 1e5f;
        g_diff[i] = fabsf(sqrtf(an_d2) - sqrtf(ap_d2)) * scale;
    }
}

// ---------------------------------------------------------------------------
// Kernel 4: deterministic final reduction + loss
// ---------------------------------------------------------------------------
__global__ __launch_bounds__(256) void finalize_kernel(float* __restrict__ out) {
    __shared__ float red[256];
    float s = 0.f;
    for (int q = threadIdx.x; q < NROW; q += 256) s += g_diff[q];
    red[threadIdx.x] = s;
    __syncthreads();
#pragma unroll
    for (int off = 128; off; off >>= 1) {
        if (threadIdx.x < off) red[threadIdx.x] += red[threadIdx.x + off];
        __syncthreads();
    }
    if (threadIdx.x == 0)
        out[0] = log10f((float)NROW / red[0]);
}

// ---------------------------------------------------------------------------
extern "C" void kernel_launch(void* const* d_in, const int* in_sizes, int n_in,
                              void* d_out, int out_size) {
    const float* X = (const float*)d_in[0];   // [8192, 256] fp32
    float* out = (float*)d_out;

    sq_kernel<<<NROW / 8, 256>>>(X);

    dim3 grid(NROW / 128, NROW / 128);
    gemm_d2_kernel<<<grid, 256>>>(X);

    select_kernel<<<NROW, 256>>>();

    finalize_kernel<<<1, 256>>>(out);
}

// round 15
// speedup vs baseline: 1.3572x; 1.3572x over previous
#include <cuda_runtime.h>
#include <cuda_bf16.h>
#include <math.h>
#include <stdint.h>

#define NROW 8192
#define DDIM 256
#define KINST 16
#define KNEG 4088   // (N-K)/2
#define KPOS 8      // K/2
#define NT 64       // 128x128 tiles per dim
#define NTRI (NT*(NT+1)/2)

// Scratch (device globals: allocation-free per harness rules)
__device__ float g_d2[(size_t)NROW * NROW];  // 256 MB pairwise clipped squared distances
__device__ float g_sq[NROW];
__device__ float g_diff[NROW];

// ---- packed f32x2 helpers (sm_103a) ---------------------------------------
__device__ __forceinline__ unsigned long long pk2(float x, float y) {
    unsigned long long r;
    asm("mov.b64 %0, {%1, %2};" : "=l"(r) : "f"(x), "f"(y));
    return r;
}
__device__ __forceinline__ void upk2(unsigned long long v, float& x, float& y) {
    asm("mov.b64 {%0, %1}, %2;" : "=f"(x), "=f"(y) : "l"(v));
}
__device__ __forceinline__ unsigned long long fma2(unsigned long long a,
                                                   unsigned long long b,
                                                   unsigned long long c) {
    unsigned long long d;
    asm("fma.rn.f32x2 %0, %1, %2, %3;" : "=l"(d) : "l"(a), "l"(b), "l"(c));
    return d;
}

// ---------------------------------------------------------------------------
// Kernel 1: row squared norms. One warp per row.
// ---------------------------------------------------------------------------
__global__ __launch_bounds__(256) void sq_kernel(const float* __restrict__ X) {
    int row = blockIdx.x * 8 + (threadIdx.x >> 5);
    int lane = threadIdx.x & 31;
    const float* r = X + (size_t)row * DDIM;
    float s = 0.f;
#pragma unroll
    for (int c = lane; c < DDIM; c += 32) {
        float v = r[c];
        s = fmaf(v, v, s);
    }
#pragma unroll
    for (int o = 16; o; o >>= 1) s += __shfl_xor_sync(0xffffffffu, s, o);
    if (lane == 0) g_sq[row] = s;
}

// ---------------------------------------------------------------------------
// Kernel 2: fp32 GEMM (upper-triangle tiles only, FFMA2 packed math)
//   d2[i][j] = max(sq_i + sq_j - 2*dot(i,j), 1e-12), mirrored to [j][i]
// 128x128 tile, BK=16, 256 threads, 8x8 micro-tile per thread.
// ---------------------------------------------------------------------------
__global__ __launch_bounds__(256, 2) void gemm_d2_kernel(const float* __restrict__ X) {
    const int BM = 128, BN = 128, BK = 16;

    __shared__ __align__(16) float SH[2 * BK * (BM + 4)];   // 4224 floats
    float (*As)[BM + 4] = (float (*)[BM + 4])SH;
    float (*Bs)[BN + 4] = (float (*)[BN + 4])(SH + BK * (BM + 4));
    float (*Ts)[132]    = (float (*)[132])SH;               // 32 x 132 staging

    // decode linear block index -> upper-triangle tile (ti <= tj)
    int idx = blockIdx.x;
    int ti = (int)floorf((float)NT + 0.5f -
                         sqrtf(((float)NT + 0.5f) * ((float)NT + 0.5f) - 2.0f * idx));
    while (ti > 0 && ti * NT - ti * (ti - 1) / 2 > idx) --ti;
    while ((ti + 1) * NT - (ti + 1) * ti / 2 <= idx) ++ti;
    int tj = ti + (idx - (ti * NT - ti * (ti - 1) / 2));

    const int bi = ti * BM;
    const int bj = tj * BN;
    const int tid = threadIdx.x;
    const int ty = tid >> 4;        // 0..15
    const int tx = tid & 15;        // 0..15

    unsigned long long acc2[8][4];
#pragma unroll
    for (int r = 0; r < 8; ++r)
#pragma unroll
        for (int c = 0; c < 4; ++c) acc2[r][c] = 0ull;

    for (int k0 = 0; k0 < DDIM; k0 += BK) {
#pragma unroll
        for (int qq = 0; qq < 2; ++qq) {
            int q   = tid + qq * 256;
            int row = q >> 2;
            int c4  = (q & 3) * 4;
            float4 va = *(const float4*)(X + (size_t)(bi + row) * DDIM + k0 + c4);
            As[c4 + 0][row] = va.x; As[c4 + 1][row] = va.y;
            As[c4 + 2][row] = va.z; As[c4 + 3][row] = va.w;
            float4 vb = *(const float4*)(X + (size_t)(bj + row) * DDIM + k0 + c4);
            Bs[c4 + 0][row] = vb.x; Bs[c4 + 1][row] = vb.y;
            Bs[c4 + 2][row] = vb.z; Bs[c4 + 3][row] = vb.w;
        }
        __syncthreads();

#pragma unroll
        for (int kk = 0; kk < BK; ++kk) {
            unsigned long long ad[8], b2[4];
#pragma unroll
            for (int u = 0; u < 8; ++u) {
                float a = As[kk][ty * 8 + u];
                ad[u] = pk2(a, a);
            }
#pragma unroll
            for (int c = 0; c < 4; ++c)
                b2[c] = *(const unsigned long long*)&Bs[kk][tx * 8 + 2 * c];
#pragma unroll
            for (int r = 0; r < 8; ++r)
#pragma unroll
                for (int c = 0; c < 4; ++c)
                    acc2[r][c] = fma2(ad[r], b2[c], acc2[r][c]);
        }
        __syncthreads();
    }

    // unpack accumulators
    float acc[8][8];
#pragma unroll
    for (int r = 0; r < 8; ++r)
#pragma unroll
        for (int c = 0; c < 4; ++c)
            upk2(acc2[r][c], acc[r][2 * c], acc[r][2 * c + 1]);

    float sqi[8], sqj[8];
#pragma unroll
    for (int u = 0; u < 8; ++u) {
        sqi[u] = g_sq[bi + ty * 8 + u];
        sqj[u] = g_sq[bj + tx * 8 + u];
    }

    // normal (upper) write: rows bi+..., cols bj+...
#pragma unroll
    for (int r = 0; r < 8; ++r) {
        size_t base = (size_t)(bi + ty * 8 + r) * NROW + bj + tx * 8;
        float v[8];
#pragma unroll
        for (int c = 0; c < 8; ++c)
            v[c] = fmaxf(sqi[r] + sqj[c] - 2.0f * acc[r][c], 1e-12f);
        *(float4*)(g_d2 + base)     = make_float4(v[0], v[1], v[2], v[3]);
        *(float4*)(g_d2 + base + 4) = make_float4(v[4], v[5], v[6], v[7]);
    }

    // mirrored (lower) write via smem transpose, 4 chunks of 32 columns
    if (ti != tj) {
#pragma unroll 1
        for (int cb = 0; cb < 4; ++cb) {
            __syncthreads();                 // Ts aliases As/Bs; also guards prev read
            if ((tx >> 2) == cb) {
#pragma unroll
                for (int c = 0; c < 8; ++c) {
                    int jl = (tx & 3) * 8 + c;     // 0..31 within chunk
#pragma unroll
                    for (int r = 0; r < 8; ++r)
                        Ts[jl][ty * 8 + r] =
                            fmaxf(sqi[r] + sqj[c] - 2.0f * acc[r][c], 1e-12f);
                }
            }
            __syncthreads();
            // write out: 32 rows (bj+cb*32+jl) x 128 cols (bi+..), coalesced float4
#pragma unroll
            for (int it = 0; it < 4; ++it) {
                int q = tid + it * 256;            // 0..1023
                int jl   = q >> 5;                 // 0..31
                int col4 = q & 31;                 // 0..31
                float4 v = *(const float4*)&Ts[jl][col4 * 4];
                *(float4*)(g_d2 + (size_t)(bj + cb * 32 + jl) * NROW + bi + col4 * 4) = v;
            }
        }
    }
}

// ---------------------------------------------------------------------------
// Kernel 3: per-row selection. One CTA (256 threads) per row.
// ---------------------------------------------------------------------------
__global__ __launch_bounds__(256) void select_kernel() {
    __shared__ float row[NROW];          // 32 KB
    __shared__ unsigned hist[256];
    __shared__ float red[256];
    __shared__ float pos_s[KINST];
    __shared__ unsigned s_prefix, s_k;

    const int i   = blockIdx.x;
    const int tid = threadIdx.x;

    const float4* src = (const float4*)(g_d2 + (size_t)i * NROW);
    float4* rw = (float4*)row;
    for (int q = tid; q < NROW / 4; q += 256) rw[q] = src[q];
    __syncthreads();

    // rn^2 : deterministic block reduce
    float s = 0.f;
    for (int q = tid; q < NROW; q += 256) s += row[q];
    red[tid] = s;
    __syncthreads();
#pragma unroll
    for (int off = 128; off; off >>= 1) {
        if (tid < off) red[tid] += red[tid + off];
        __syncthreads();
    }

    // positives = own identity group; save then zero
    const int g0 = i & ~(KINST - 1);
    if (tid < KINST) pos_s[tid] = row[g0 + tid];
    __syncthreads();
    if (tid < KINST) row[g0 + tid] = 0.0f;
    if (tid == 0) { s_prefix = 0u; s_k = KNEG; }
    __syncthreads();

    // exact 4x8-bit MSB-first radix select of k-th largest (all values > 0)
#pragma unroll 1
    for (int pass = 3; pass >= 0; --pass) {
        hist[tid] = 0u;
        __syncthreads();
        const unsigned prefix = s_prefix;
        const int shift = pass * 8;
        const unsigned himask = (pass == 3) ? 0u : (0xFFFFFFFFu << (shift + 8));
        const unsigned lane = tid & 31;

        for (int q = tid; q < NROW; q += 256) {
            unsigned b = __float_as_uint(row[q]);
            unsigned key = ((b & himask) == prefix) ? ((b >> shift) & 0xFFu)
                                                    : 0xFFFFFFFFu;
            unsigned m = __match_any_sync(0xFFFFFFFFu, key);
            if (key != 0xFFFFFFFFu && (((1u << lane) - 1u) & m) == 0u)
                atomicAdd(&hist[key], (unsigned)__popc(m));
        }
        __syncthreads();

        if (tid == 0) {
            unsigned cum = 0, kk = s_k, sel = 0;
            for (int d = 255; d >= 0; --d) {
                unsigned h = hist[d];
                if (cum + h >= kk) { sel = (unsigned)d; s_k = kk - cum; break; }
                cum += h;
            }
            s_prefix = prefix | (sel << shift);
        }
        __syncthreads();
    }

    if (tid == 0) {
        float an_d2 = __uint_as_float(s_prefix);

        float p[KINST];
#pragma unroll
        for (int u = 0; u < KINST; ++u) p[u] = pos_s[u];
#pragma unroll
        for (int a = 1; a < KINST; ++a) {          // descending insertion sort
            float v = p[a];
            int b = a - 1;
            while (b >= 0 && p[b] < v) { p[b + 1] = p[b]; --b; }
            p[b + 1] = v;
        }
        float ap_d2 = p[KPOS - 1];

        float rn = sqrtf(red[0]);
        float scale = (rn > 1e-5f ? 1e-5f / rn : 1.0f) * 1e5f;
        g_diff[i] = fabsf(sqrtf(an_d2) - sqrtf(ap_d2)) * scale;
    }
}

// ---------------------------------------------------------------------------
// Kernel 4: deterministic final reduction + loss
// ---------------------------------------------------------------------------
__global__ __launch_bounds__(256) void finalize_kernel(float* __restrict__ out) {
    __shared__ float red[256];
    float s = 0.f;
    for (int q = threadIdx.x; q < NROW; q += 256) s += g_diff[q];
    red[threadIdx.x] = s;
    __syncthreads();
#pragma unroll
    for (int off = 128; off; off >>= 1) {
        if (threadIdx.x < off) red[threadIdx.x] += red[threadIdx.x + off];
        __syncthreads();
    }
    if (threadIdx.x == 0)
        out[0] = log10f((float)NROW / red[0]);
}

// ---------------------------------------------------------------------------
extern "C" void kernel_launch(void* const* d_in, const int* in_sizes, int n_in,
                              void* d_out, int out_size) {
    const float* X = (const float*)d_in[0];   // [8192, 256] fp32
    float* out = (float*)d_out;

    sq_kernel<<<NROW / 8, 256>>>(X);
    gemm_d2_kernel<<<NTRI, 256>>>(X);
    select_kernel<<<NROW, 256>>>();
    finalize_kernel<<<1, 256>>>(out);
}